// round 16
// baseline (speedup 1.0000x reference)
#include <cuda_runtime.h>
#include <cstdint>

#define D      512
#define BATCH  256
#define TOPK   2
#define NEXP   16
#define NPAIR  (BATCH * TOPK)
#define ROWS_C 64          // rows per chunk
#define CMAX   2           // chunks per expert (capacity 128 pairs/expert)
#define NKS    4           // k-splits
#define KSL    (D / NKS)   // 128 kk per split (single staged tile)
#define XSTR   132         // uint32 per row in xs: 132 mod 32 == 4 -> conflict-free frags

// ---------------- scratch (per-split partial buffers) ----------------
__device__ float g_iv[NKS * NPAIR * D];
__device__ float g_ov[NKS * NPAIR * D];
__device__ float g_dv[NKS * NPAIR * D];
__device__ float g_bv[NKS * NPAIR * D];

// ---------------- tf32 helpers ----------------
__device__ __forceinline__ uint32_t f2tf32(float f) {
    uint32_t r;
    asm("cvt.rna.tf32.f32 %0, %1;" : "=r"(r) : "f"(f));
    return r;
}
__device__ __forceinline__ void mma_tf32(float* d, const uint32_t* a, const uint32_t* b) {
    asm volatile(
        "mma.sync.aligned.m16n8k8.row.col.f32.tf32.tf32.f32 "
        "{%0,%1,%2,%3}, {%4,%5,%6,%7}, {%8,%9}, {%0,%1,%2,%3};"
        : "+f"(d[0]), "+f"(d[1]), "+f"(d[2]), "+f"(d[3])
        : "r"(a[0]), "r"(a[1]), "r"(a[2]), "r"(a[3]), "r"(b[0]), "r"(b[1]));
}

// ---------------- kernel 1: grouped GEMM, sortless (in-block ballot scan) -----------
// grid = (4 col-tiles of 128, NEXP*CMAX, 4 banks * 4 ksplits), block = 128 (4 warps).
// Each block scans the 512 expert indices (1 LDG.128/thread + warp-prefix, ~400cyc),
// collecting pairs with idx==e ranked stably by pair id; chunk c takes ranks
// [c*64, c*64+64). No sort kernel. Then 64x128-col x 128-k tf32 MMA into the
// ks-split partial buffer. W traffic: one 128-col x 128-k stream per block.
__global__ __launch_bounds__(128) void gemm_kernel(
    const float* __restrict__ x,
    const float* __restrict__ iw, const float* __restrict__ ow,
    const float* __restrict__ dw, const float* __restrict__ bb,
    const int* __restrict__ widx, const int* __restrict__ bidx) {

    __shared__ __align__(16) uint32_t xs[ROWS_C * XSTR];   // 33.8KB tf32 bits
    __shared__ int slist[ROWS_C];
    __shared__ int warpcnt[4];

    int e    = blockIdx.y >> 1;
    int c    = blockIdx.y & (CMAX - 1);
    int z    = blockIdx.z;
    int bank = z & 3;
    int ks   = z >> 2;
    int koff = ks * KSL;
    bool isW = bank < 3;

    const int* idx = isW ? widx : bidx;
    const float* W = ((bank == 0) ? iw : (bank == 1) ? ow : (bank == 2) ? dw : bb)
                     + (size_t)e * D * D;
    float* out = ((bank == 0) ? g_iv : (bank == 1) ? g_ov : (bank == 2) ? g_dv : g_bv)
                 + (size_t)ks * NPAIR * D;

    int t    = threadIdx.x;
    int lane = t & 31;
    int wid  = t >> 5;

    // ---- ballot scan: build slist for (e, chunk c) ----
    int4 v4i = ((const int4*)idx)[t];            // pairs 4t .. 4t+3
    int m0 = (v4i.x == e), m1 = (v4i.y == e), m2 = (v4i.z == e), m3 = (v4i.w == e);
    int mcnt = m0 + m1 + m2 + m3;
    int pre = mcnt;
#pragma unroll
    for (int sft = 1; sft < 32; sft <<= 1) {
        int o = __shfl_up_sync(0xffffffffu, pre, sft);
        if (lane >= sft) pre += o;
    }
    int excl = pre - mcnt;
    if (lane == 31) warpcnt[wid] = pre;
    __syncthreads();
    int base = 0;
#pragma unroll
    for (int w = 0; w < 4; w++) base += (w < wid) ? warpcnt[w] : 0;
    int total = warpcnt[0] + warpcnt[1] + warpcnt[2] + warpcnt[3];
    int lo = c * ROWS_C;
    int rows = min(ROWS_C, total - lo);
    {
        int r = base + excl;
        if (m0) { int rr = r - lo; if (rr >= 0 && rr < ROWS_C) slist[rr] = 4 * t;     r++; }
        if (m1) { int rr = r - lo; if (rr >= 0 && rr < ROWS_C) slist[rr] = 4 * t + 1; r++; }
        if (m2) { int rr = r - lo; if (rr >= 0 && rr < ROWS_C) slist[rr] = 4 * t + 2; r++; }
        if (m3) { int rr = r - lo; if (rr >= 0 && rr < ROWS_C) slist[rr] = 4 * t + 3; r++; }
    }
    __syncthreads();
    if (rows <= 0) return;   // uniform: every thread sees the same 'rows'

    // ---- stage x tile [64 rows x 128 k] as tf32 bits (coalesced: k = t) ----
#pragma unroll 4
    for (int i = 0; i < ROWS_C; i++) {
        float val = 0.0f;
        if (i < rows) val = x[(slist[i] >> 1) * D + koff + t];
        xs[i * XSTR + t] = f2tf32(val);
    }
    __syncthreads();

    int grp = lane >> 2;     // 0..7
    int tg  = lane & 3;      // 0..3
    int col0w = blockIdx.x * 128 + wid * 32;

    float d[4][4][4];
#pragma unroll
    for (int tm = 0; tm < 4; tm++)
#pragma unroll
        for (int tn = 0; tn < 4; tn++)
#pragma unroll
            for (int r = 0; r < 4; r++) d[tm][tn][r] = 0.0f;

    const float* Wk = W + (size_t)(koff + tg) * D + col0w + grp;

#pragma unroll 4
    for (int k8 = 0; k8 < KSL / 8; k8++) {
        int kb = k8 * 8;
        // A fragments (tf32 bits from smem, conflict-free stride-132)
        uint32_t a[4][4];
#pragma unroll
        for (int tm = 0; tm < 4; tm++) {
            int rbase = tm * 16 + grp;
            a[tm][0] = xs[(rbase)     * XSTR + kb + tg];
            a[tm][1] = xs[(rbase + 8) * XSTR + kb + tg];
            a[tm][2] = xs[(rbase)     * XSTR + kb + tg + 4];
            a[tm][3] = xs[(rbase + 8) * XSTR + kb + tg + 4];
        }
        // B fragments (direct gmem + cvt.rna)
        uint32_t b[4][2];
#pragma unroll
        for (int tn = 0; tn < 4; tn++) {
            float b0 = Wk[(size_t)kb * D + tn * 8];
            float b1 = Wk[(size_t)(kb + 4) * D + tn * 8];
            b[tn][0] = f2tf32(b0);
            b[tn][1] = f2tf32(b1);
        }
#pragma unroll
        for (int tm = 0; tm < 4; tm++)
#pragma unroll
            for (int tn = 0; tn < 4; tn++)
                mma_tf32(d[tm][tn], a[tm], b[tn]);
    }

    // store: d[tm][tn] covers rows {tm*16+grp, +8} x cols {col0w+tn*8+tg*2, +1}
#pragma unroll
    for (int tm = 0; tm < 4; tm++) {
#pragma unroll
        for (int tn = 0; tn < 4; tn++) {
            int col = col0w + tn * 8 + tg * 2;
            int row0 = tm * 16 + grp;
            int row1 = row0 + 8;
            if (row0 < rows) {
                float2 vv = make_float2(d[tm][tn][0], d[tm][tn][1]);
                *(float2*)&out[(size_t)slist[row0] * D + col] = vv;
            }
            if (row1 < rows) {
                float2 vv = make_float2(d[tm][tn][2], d[tm][tn][3]);
                *(float2*)&out[(size_t)slist[row1] * D + col] = vv;
            }
        }
    }
}

// ---------------- kernel 2: sum 4 k-splits + rank-2 mix + analytic LN + bmix -------
__global__ __launch_bounds__(128) void mix_ln_kernel(
    const float* __restrict__ wp, const float* __restrict__ bp,
    float* __restrict__ outp) {

    int b  = blockIdx.y;
    int r0 = blockIdx.x * 128;
    int t  = threadIdx.x;

    __shared__ float u[D], v[D];
    __shared__ __align__(16) float4 sparams[128];   // {pr, qr, c, gr}
    __shared__ float red[4][5];

    float4 u4 = make_float4(0.f, 0.f, 0.f, 0.f);
    float4 v4 = make_float4(0.f, 0.f, 0.f, 0.f);
#pragma unroll
    for (int ks = 0; ks < NKS; ks++) {
        const float* basep = g_ov + (size_t)ks * NPAIR * D;
        float4 a = ((const float4*)(basep + (size_t)(2 * b) * D))[t];
        float4 cc = ((const float4*)(basep + (size_t)(2 * b + 1) * D))[t];
        u4.x += a.x; u4.y += a.y; u4.z += a.z; u4.w += a.w;
        v4.x += cc.x; v4.y += cc.y; v4.z += cc.z; v4.w += cc.w;
    }
    ((float4*)u)[t] = u4;
    ((float4*)v)[t] = v4;

    float lu  = u4.x + u4.y + u4.z + u4.w;
    float lv  = v4.x + v4.y + v4.z + v4.w;
    float luu = u4.x * u4.x + u4.y * u4.y + u4.z * u4.z + u4.w * u4.w;
    float lvv = v4.x * v4.x + v4.y * v4.y + v4.z * v4.z + v4.w * v4.w;
    float luv = u4.x * v4.x + u4.y * v4.y + u4.z * v4.z + u4.w * v4.w;
#pragma unroll
    for (int sft = 16; sft > 0; sft >>= 1) {
        lu  += __shfl_xor_sync(0xffffffffu, lu, sft);
        lv  += __shfl_xor_sync(0xffffffffu, lv, sft);
        luu += __shfl_xor_sync(0xffffffffu, luu, sft);
        lvv += __shfl_xor_sync(0xffffffffu, lvv, sft);
        luv += __shfl_xor_sync(0xffffffffu, luv, sft);
    }
    int lane = t & 31, wrp = t >> 5;
    if (lane == 0) {
        red[wrp][0] = lu; red[wrp][1] = lv; red[wrp][2] = luu;
        red[wrp][3] = lvv; red[wrp][4] = luv;
    }
    __syncthreads();
    float Su  = red[0][0] + red[1][0] + red[2][0] + red[3][0];
    float Sv  = red[0][1] + red[1][1] + red[2][1] + red[3][1];
    float Suu = red[0][2] + red[1][2] + red[2][2] + red[3][2];
    float Svv = red[0][3] + red[1][3] + red[2][3] + red[3][3];
    float Suv = red[0][4] + red[1][4] + red[2][4] + red[3][4];

    {
        int i = r0 + t;
        float iv0 = 0.f, iv1 = 0.f, dv0 = 0.f, dv1 = 0.f;
#pragma unroll
        for (int ks = 0; ks < NKS; ks++) {
            size_t off = (size_t)ks * NPAIR * D;
            iv0 += g_iv[off + (size_t)(2 * b) * D + i];
            iv1 += g_iv[off + (size_t)(2 * b + 1) * D + i];
            dv0 += g_dv[off + (size_t)(2 * b) * D + i];
            dv1 += g_dv[off + (size_t)(2 * b + 1) * D + i];
        }
        float wp0 = wp[2 * b], wp1 = wp[2 * b + 1];
        float p = wp0 * iv0;
        float q = wp1 * iv1;
        float g = wp0 * dv0 + wp1 * dv1;
        const float invD = 1.0f / (float)D;
        float mean = (p * Su + q * Sv + g) * invD;
        float ex2  = (p * p * Suu + 2.0f * p * q * Suv + q * q * Svv
                      + 2.0f * g * (p * u[i] + q * v[i]) + g * g) * invD;
        float var  = ex2 - mean * mean;
        float rstd = rsqrtf(var + 1e-5f);
        float4 pr;
        pr.x = p * rstd;
        pr.y = q * rstd;
        pr.z = -mean * rstd;
        pr.w = g * rstd;
        sparams[t] = pr;
    }
    __syncthreads();

    float* orow = outp + ((size_t)b * D + r0) * D + (t << 2);

    if (wrp == blockIdx.x) {
        int base = t << 2;
#pragma unroll 4
        for (int r = 0; r < 128; r++) {
            float4 P = sparams[r];
            float4 o;
            o.x = fmaf(P.y, v4.x, fmaf(P.x, u4.x, P.z));
            o.y = fmaf(P.y, v4.y, fmaf(P.x, u4.y, P.z));
            o.z = fmaf(P.y, v4.z, fmaf(P.x, u4.z, P.z));
            o.w = fmaf(P.y, v4.w, fmaf(P.x, u4.w, P.z));
            int dj = (r0 + r) - base;
            if (dj == 0) o.x += P.w;
            if (dj == 1) o.y += P.w;
            if (dj == 2) o.z += P.w;
            if (dj == 3) o.w += P.w;
            *(float4*)(orow + (size_t)r * D) = o;
        }
    } else {
#pragma unroll 4
        for (int r = 0; r < 128; r++) {
            float4 P = sparams[r];
            float4 o;
            o.x = fmaf(P.y, v4.x, fmaf(P.x, u4.x, P.z));
            o.y = fmaf(P.y, v4.y, fmaf(P.x, u4.y, P.z));
            o.z = fmaf(P.y, v4.z, fmaf(P.x, u4.z, P.z));
            o.w = fmaf(P.y, v4.w, fmaf(P.x, u4.w, P.z));
            *(float4*)(orow + (size_t)r * D) = o;
        }
    }

    // bmix (row-tile 0 only): bmix[b,:] = bp0*sum(bv0) + bp1*sum(bv1)
    if (blockIdx.x == 0) {
        float bp0 = bp[2 * b], bp1 = bp[2 * b + 1];
        float4 s0 = make_float4(0.f, 0.f, 0.f, 0.f);
        float4 s1 = make_float4(0.f, 0.f, 0.f, 0.f);
#pragma unroll
        for (int ks = 0; ks < NKS; ks++) {
            const float* basep = g_bv + (size_t)ks * NPAIR * D;
            float4 a = ((const float4*)(basep + (size_t)(2 * b) * D))[t];
            float4 cc = ((const float4*)(basep + (size_t)(2 * b + 1) * D))[t];
            s0.x += a.x; s0.y += a.y; s0.z += a.z; s0.w += a.w;
            s1.x += cc.x; s1.y += cc.y; s1.z += cc.z; s1.w += cc.w;
        }
        float4 o;
        o.x = bp0 * s0.x + bp1 * s1.x;
        o.y = bp0 * s0.y + bp1 * s1.y;
        o.z = bp0 * s0.z + bp1 * s1.z;
        o.w = bp0 * s0.w + bp1 * s1.w;
        ((float4*)(outp + (size_t)BATCH * D * D + (size_t)b * D))[t] = o;
    }
}

// ---------------- launch ----------------
extern "C" void kernel_launch(void* const* d_in, const int* in_sizes, int n_in,
                              void* d_out, int out_size) {
    const float* x    = (const float*)d_in[0];
    const float* wp   = (const float*)d_in[1];
    const float* bpr  = (const float*)d_in[2];
    const float* iw   = (const float*)d_in[3];
    const float* ow   = (const float*)d_in[4];
    const float* dw   = (const float*)d_in[5];
    const float* bb   = (const float*)d_in[6];
    const int*   widx = (const int*)d_in[7];
    const int*   bidx = (const int*)d_in[8];
    float* outp = (float*)d_out;

    gemm_kernel<<<dim3(4, NEXP * CMAX, 4 * NKS), 128>>>(x, iw, ow, dw, bb, widx, bidx);
    mix_ln_kernel<<<dim3(4, BATCH), 128>>>(wp, bpr, outp);
}

// round 17
// speedup vs baseline: 1.0944x; 1.0944x over previous
#include <cuda_runtime.h>
#include <cstdint>

#define D      512
#define BATCH  256
#define TOPK   2
#define NEXP   16
#define NPAIR  (BATCH * TOPK)
#define MAXCH  32          // worst-case sum ceil(M_e/32) over 16 experts = 31
#define ROWS_C 32          // rows per chunk
#define NKS    4           // k-splits
#define KSL    (D / NKS)   // 128 kk per split (single staged tile)
#define XSTR   132         // uint32 per row in xs: 132 mod 32 == 4 -> conflict-free frags

// ---------------- scratch (per-split partial buffers) ----------------
__device__ float g_iv[NKS * NPAIR * D];
__device__ float g_ov[NKS * NPAIR * D];
__device__ float g_dv[NKS * NPAIR * D];
__device__ float g_bv[NKS * NPAIR * D];
__device__ int   g_list_w[NPAIR];
__device__ int   g_list_b[NPAIR];
__device__ int   g_chunks_w[MAXCH];   // packed: start | e<<16 | rows<<24
__device__ int   g_chunks_b[MAXCH];
__device__ int   g_nch_w, g_nch_b;

// ---------------- kernel 0: counting sort + 32-row chunk work-list ----------------
__global__ void sort_kernel(const int* __restrict__ widx, const int* __restrict__ bidx) {
    __shared__ int cw[NEXP], cb[NEXP], offw[NEXP + 1], offb[NEXP + 1], pw[NEXP], pb[NEXP];
    int t = threadIdx.x;                       // 512 threads == pair id
    if (t < NEXP) { cw[t] = 0; cb[t] = 0; }
    __syncthreads();
    int ew = widx[t];
    int eb = bidx[t];
    atomicAdd(&cw[ew], 1);
    atomicAdd(&cb[eb], 1);
    __syncthreads();
    if (t == 0) {
        int s = 0;
        for (int e = 0; e < NEXP; e++) { offw[e] = s; s += cw[e]; }
        offw[NEXP] = s;
        int n = 0;
        for (int e = 0; e < NEXP; e++)
            for (int c = offw[e]; c < offw[e + 1]; c += ROWS_C) {
                int rows = min(ROWS_C, offw[e + 1] - c);
                g_chunks_w[n++] = c | (e << 16) | (rows << 24);
            }
        g_nch_w = n;
    }
    if (t == 32) {
        int s = 0;
        for (int e = 0; e < NEXP; e++) { offb[e] = s; s += cb[e]; }
        offb[NEXP] = s;
        int n = 0;
        for (int e = 0; e < NEXP; e++)
            for (int c = offb[e]; c < offb[e + 1]; c += ROWS_C) {
                int rows = min(ROWS_C, offb[e + 1] - c);
                g_chunks_b[n++] = c | (e << 16) | (rows << 24);
            }
        g_nch_b = n;
    }
    __syncthreads();
    if (t < NEXP) { pw[t] = offw[t]; pb[t] = offb[t]; }
    __syncthreads();
    int posw = atomicAdd(&pw[ew], 1);
    g_list_w[posw] = t;
    int posb = atomicAdd(&pb[eb], 1);
    g_list_b[posb] = t;
}

// ---------------- tf32 helpers ----------------
__device__ __forceinline__ uint32_t f2tf32(float f) {
    uint32_t r;
    asm("cvt.rna.tf32.f32 %0, %1;" : "=r"(r) : "f"(f));
    return r;
}
__device__ __forceinline__ void mma_tf32(float* d, const uint32_t* a, const uint32_t* b) {
    asm volatile(
        "mma.sync.aligned.m16n8k8.row.col.f32.tf32.tf32.f32 "
        "{%0,%1,%2,%3}, {%4,%5,%6,%7}, {%8,%9}, {%0,%1,%2,%3};"
        : "+f"(d[0]), "+f"(d[1]), "+f"(d[2]), "+f"(d[3])
        : "r"(a[0]), "r"(a[1]), "r"(a[2]), "r"(a[3]), "r"(b[0]), "r"(b[1]));
}

// ---------------- kernel 1: grouped GEMM via tf32 mma.sync + split-K=4 -------------
// grid = (4 col-tiles of 128, MAXCH chunks, 4 banks * 4 ksplits) ~ 1984 active blocks
// (~13/SM), block = 128 (4 warps). Warp w: rows 0..31 (2 x m16) x cols [32w,32w+32)
// (4 x n8); block covers K in [ks*128, ks*128+128) — one staged tile, no kt loop.
// A frags from smem (tf32 bits, stride-132 conflict-free); B frags direct from gmem.
__global__ __launch_bounds__(128) void gemm_kernel(
    const float* __restrict__ x,
    const float* __restrict__ iw, const float* __restrict__ ow,
    const float* __restrict__ dw, const float* __restrict__ bb) {

    int z    = blockIdx.z;
    int bank = z & 3;
    int ks   = z >> 2;
    int koff = ks * KSL;
    bool isW = bank < 3;
    int nch = isW ? g_nch_w : g_nch_b;
    if ((int)blockIdx.y >= nch) return;

    __shared__ __align__(16) uint32_t xs[ROWS_C * XSTR];   // 16.9KB tf32 bits

    int packed = (isW ? g_chunks_w : g_chunks_b)[blockIdx.y];
    int s    = packed & 0xFFFF;
    int e    = (packed >> 16) & 0xFF;
    int rows = (packed >> 24) & 0xFF;

    const int* list = isW ? g_list_w : g_list_b;
    const float* W  = ((bank == 0) ? iw : (bank == 1) ? ow : (bank == 2) ? dw : bb)
                      + (size_t)e * D * D;
    float* out = ((bank == 0) ? g_iv : (bank == 1) ? g_ov : (bank == 2) ? g_dv : g_bv)
                 + (size_t)ks * NPAIR * D;

    int t    = threadIdx.x;
    int lane = t & 31;
    int wid  = t >> 5;
    int grp  = lane >> 2;     // 0..7
    int tg   = lane & 3;      // 0..3
    int col0w = blockIdx.x * 128 + wid * 32;

    // stage x tile [32 rows x 128 k] as tf32 bits (coalesced: k = t)
#pragma unroll 4
    for (int i = 0; i < ROWS_C; i++) {
        float val = 0.0f;
        if (i < rows) val = x[(list[s + i] >> 1) * D + koff + t];
        xs[i * XSTR + t] = f2tf32(val);
    }
    __syncthreads();

    float d[2][4][4];
#pragma unroll
    for (int tm = 0; tm < 2; tm++)
#pragma unroll
        for (int tn = 0; tn < 4; tn++)
#pragma unroll
            for (int r = 0; r < 4; r++) d[tm][tn][r] = 0.0f;

    const float* Wk = W + (size_t)(koff + tg) * D + col0w + grp;

#pragma unroll 4
    for (int k8 = 0; k8 < KSL / 8; k8++) {
        int kb = k8 * 8;
        // A fragments (tf32 bits from smem)
        uint32_t a[2][4];
#pragma unroll
        for (int tm = 0; tm < 2; tm++) {
            int rbase = tm * 16 + grp;
            a[tm][0] = xs[(rbase)     * XSTR + kb + tg];
            a[tm][1] = xs[(rbase + 8) * XSTR + kb + tg];
            a[tm][2] = xs[(rbase)     * XSTR + kb + tg + 4];
            a[tm][3] = xs[(rbase + 8) * XSTR + kb + tg + 4];
        }
        // B fragments (direct gmem + cvt.rna)
        uint32_t b[4][2];
#pragma unroll
        for (int tn = 0; tn < 4; tn++) {
            float b0 = Wk[(size_t)kb * D + tn * 8];
            float b1 = Wk[(size_t)(kb + 4) * D + tn * 8];
            b[tn][0] = f2tf32(b0);
            b[tn][1] = f2tf32(b1);
        }
        // 8 MMAs
#pragma unroll
        for (int tm = 0; tm < 2; tm++)
#pragma unroll
            for (int tn = 0; tn < 4; tn++)
                mma_tf32(d[tm][tn], a[tm], b[tn]);
    }

    // store: d[tm][tn] covers rows {tm*16+grp, +8} x cols {col0w+tn*8+tg*2, +1}
#pragma unroll
    for (int tm = 0; tm < 2; tm++) {
#pragma unroll
        for (int tn = 0; tn < 4; tn++) {
            int col = col0w + tn * 8 + tg * 2;
            int row0 = tm * 16 + grp;
            int row1 = row0 + 8;
            if (row0 < rows) {
                float2 v = make_float2(d[tm][tn][0], d[tm][tn][1]);
                *(float2*)&out[(size_t)list[s + row0] * D + col] = v;
            }
            if (row1 < rows) {
                float2 v = make_float2(d[tm][tn][2], d[tm][tn][3]);
                *(float2*)&out[(size_t)list[s + row1] * D + col] = v;
            }
        }
    }
}

// ---------------- kernel 2: sum 4 k-splits + rank-2 mix + analytic LN + bmix -------
// r16-measured at 50.1us (DRAM 57.5%): the partial-sum reads interleave with the
// write stream and raise achieved HBM utilization.
__global__ __launch_bounds__(128) void mix_ln_kernel(
    const float* __restrict__ wp, const float* __restrict__ bp,
    float* __restrict__ outp) {

    int b  = blockIdx.y;
    int r0 = blockIdx.x * 128;
    int t  = threadIdx.x;

    __shared__ float u[D], v[D];
    __shared__ __align__(16) float4 sparams[128];   // {pr, qr, c, gr}
    __shared__ float red[4][5];

    float4 u4 = make_float4(0.f, 0.f, 0.f, 0.f);
    float4 v4 = make_float4(0.f, 0.f, 0.f, 0.f);
#pragma unroll
    for (int ks = 0; ks < NKS; ks++) {
        const float* basep = g_ov + (size_t)ks * NPAIR * D;
        float4 a = ((const float4*)(basep + (size_t)(2 * b) * D))[t];
        float4 cc = ((const float4*)(basep + (size_t)(2 * b + 1) * D))[t];
        u4.x += a.x; u4.y += a.y; u4.z += a.z; u4.w += a.w;
        v4.x += cc.x; v4.y += cc.y; v4.z += cc.z; v4.w += cc.w;
    }
    ((float4*)u)[t] = u4;
    ((float4*)v)[t] = v4;

    float lu  = u4.x + u4.y + u4.z + u4.w;
    float lv  = v4.x + v4.y + v4.z + v4.w;
    float luu = u4.x * u4.x + u4.y * u4.y + u4.z * u4.z + u4.w * u4.w;
    float lvv = v4.x * v4.x + v4.y * v4.y + v4.z * v4.z + v4.w * v4.w;
    float luv = u4.x * v4.x + u4.y * v4.y + u4.z * v4.z + u4.w * v4.w;
#pragma unroll
    for (int sft = 16; sft > 0; sft >>= 1) {
        lu  += __shfl_xor_sync(0xffffffffu, lu, sft);
        lv  += __shfl_xor_sync(0xffffffffu, lv, sft);
        luu += __shfl_xor_sync(0xffffffffu, luu, sft);
        lvv += __shfl_xor_sync(0xffffffffu, lvv, sft);
        luv += __shfl_xor_sync(0xffffffffu, luv, sft);
    }
    int lane = t & 31, wrp = t >> 5;
    if (lane == 0) {
        red[wrp][0] = lu; red[wrp][1] = lv; red[wrp][2] = luu;
        red[wrp][3] = lvv; red[wrp][4] = luv;
    }
    __syncthreads();
    float Su  = red[0][0] + red[1][0] + red[2][0] + red[3][0];
    float Sv  = red[0][1] + red[1][1] + red[2][1] + red[3][1];
    float Suu = red[0][2] + red[1][2] + red[2][2] + red[3][2];
    float Svv = red[0][3] + red[1][3] + red[2][3] + red[3][3];
    float Suv = red[0][4] + red[1][4] + red[2][4] + red[3][4];

    {
        int i = r0 + t;
        float iv0 = 0.f, iv1 = 0.f, dv0 = 0.f, dv1 = 0.f;
#pragma unroll
        for (int ks = 0; ks < NKS; ks++) {
            size_t off = (size_t)ks * NPAIR * D;
            iv0 += g_iv[off + (size_t)(2 * b) * D + i];
            iv1 += g_iv[off + (size_t)(2 * b + 1) * D + i];
            dv0 += g_dv[off + (size_t)(2 * b) * D + i];
            dv1 += g_dv[off + (size_t)(2 * b + 1) * D + i];
        }
        float wp0 = wp[2 * b], wp1 = wp[2 * b + 1];
        float p = wp0 * iv0;
        float q = wp1 * iv1;
        float g = wp0 * dv0 + wp1 * dv1;
        const float invD = 1.0f / (float)D;
        float mean = (p * Su + q * Sv + g) * invD;
        float ex2  = (p * p * Suu + 2.0f * p * q * Suv + q * q * Svv
                      + 2.0f * g * (p * u[i] + q * v[i]) + g * g) * invD;
        float var  = ex2 - mean * mean;
        float rstd = rsqrtf(var + 1e-5f);
        float4 pr;
        pr.x = p * rstd;
        pr.y = q * rstd;
        pr.z = -mean * rstd;
        pr.w = g * rstd;
        sparams[t] = pr;
    }
    __syncthreads();

    float* orow = outp + ((size_t)b * D + r0) * D + (t << 2);

    if (wrp == blockIdx.x) {
        int base = t << 2;
#pragma unroll 4
        for (int r = 0; r < 128; r++) {
            float4 P = sparams[r];
            float4 o;
            o.x = fmaf(P.y, v4.x, fmaf(P.x, u4.x, P.z));
            o.y = fmaf(P.y, v4.y, fmaf(P.x, u4.y, P.z));
            o.z = fmaf(P.y, v4.z, fmaf(P.x, u4.z, P.z));
            o.w = fmaf(P.y, v4.w, fmaf(P.x, u4.w, P.z));
            int dj = (r0 + r) - base;
            if (dj == 0) o.x += P.w;
            if (dj == 1) o.y += P.w;
            if (dj == 2) o.z += P.w;
            if (dj == 3) o.w += P.w;
            *(float4*)(orow + (size_t)r * D) = o;
        }
    } else {
#pragma unroll 4
        for (int r = 0; r < 128; r++) {
            float4 P = sparams[r];
            float4 o;
            o.x = fmaf(P.y, v4.x, fmaf(P.x, u4.x, P.z));
            o.y = fmaf(P.y, v4.y, fmaf(P.x, u4.y, P.z));
            o.z = fmaf(P.y, v4.z, fmaf(P.x, u4.z, P.z));
            o.w = fmaf(P.y, v4.w, fmaf(P.x, u4.w, P.z));
            *(float4*)(orow + (size_t)r * D) = o;
        }
    }

    // bmix (row-tile 0 only): bmix[b,:] = bp0*sum(bv0) + bp1*sum(bv1)
    if (blockIdx.x == 0) {
        float bp0 = bp[2 * b], bp1 = bp[2 * b + 1];
        float4 s0 = make_float4(0.f, 0.f, 0.f, 0.f);
        float4 s1 = make_float4(0.f, 0.f, 0.f, 0.f);
#pragma unroll
        for (int ks = 0; ks < NKS; ks++) {
            const float* basep = g_bv + (size_t)ks * NPAIR * D;
            float4 a = ((const float4*)(basep + (size_t)(2 * b) * D))[t];
            float4 cc = ((const float4*)(basep + (size_t)(2 * b + 1) * D))[t];
            s0.x += a.x; s0.y += a.y; s0.z += a.z; s0.w += a.w;
            s1.x += cc.x; s1.y += cc.y; s1.z += cc.z; s1.w += cc.w;
        }
        float4 o;
        o.x = bp0 * s0.x + bp1 * s1.x;
        o.y = bp0 * s0.y + bp1 * s1.y;
        o.z = bp0 * s0.z + bp1 * s1.z;
        o.w = bp0 * s0.w + bp1 * s1.w;
        ((float4*)(outp + (size_t)BATCH * D * D + (size_t)b * D))[t] = o;
    }
}

// ---------------- launch ----------------
extern "C" void kernel_launch(void* const* d_in, const int* in_sizes, int n_in,
                              void* d_out, int out_size) {
    const float* x    = (const float*)d_in[0];
    const float* wp   = (const float*)d_in[1];
    const float* bpr  = (const float*)d_in[2];
    const float* iw   = (const float*)d_in[3];
    const float* ow   = (const float*)d_in[4];
    const float* dw   = (const float*)d_in[5];
    const float* bb   = (const float*)d_in[6];
    const int*   widx = (const int*)d_in[7];
    const int*   bidx = (const int*)d_in[8];
    float* outp = (float*)d_out;

    sort_kernel<<<1, NPAIR>>>(widx, bidx);
    gemm_kernel<<<dim3(4, MAXCH, 4 * NKS), 128>>>(x, iw, ow, dw, bb);
    mix_ln_kernel<<<dim3(4, BATCH), 128>>>(wp, bpr, outp);
}